// round 9
// baseline (speedup 1.0000x reference)
#include <cuda_runtime.h>
#include <math.h>

#define NV 3
#define NA 4
#define NN 50000
#define NC 128
#define NVA   (NV * NA)          // 12
#define TOTAL (NA * NN)          // 200000 node-jobs
#define NBLK  148                // <= SM count: single wave, grid barrier safe
#define NTHR  1024
#define NWARP (NTHR / 32)

// Persistent scratch. Initial values are 0 (module load); the kernel restores
// all of them to 0 before exiting, so every graph replay sees a clean state.
__device__ float    g_s[NVA * NC];
__device__ float    g_u[NVA * NC];
__device__ float    g_t[NVA];
__device__ unsigned g_bar1;
__device__ unsigned g_flag;
__device__ unsigned g_bar2;

__global__ __launch_bounds__(NTHR, 1) void fused_kernel(
    const float* __restrict__ x,    // [V,A,N,C]
    const float* __restrict__ W,    // [V,C,C]
    const float* __restrict__ b,    // [V,C]
    float* __restrict__ out)        // [A,N,C]
{
    const int tid  = threadIdx.x;
    const int lane = tid & 31;
    const int warp = tid >> 5;
    const int blk  = blockIdx.x;

    __shared__ float4 red[NWARP * 32];   // 16 KB (reused as sh_s by block 0)
    __shared__ float4 sh_u[NVA * 32];    // 6 KB
    __shared__ float  sh_t[NVA];

    const float4* __restrict__ x4 = reinterpret_cast<const float4*>(x);

    // ---------------- Phase 1: column sums over nodes ----------------
    const int rows = (NN + NBLK - 1) / NBLK;    // 338
    const int n0   = blk * rows;
    const int n1   = min(n0 + rows, NN);

    for (int va = 0; va < NVA; ++va) {
        const float4* __restrict__ p = x4 + (size_t)va * NN * 32;
        float4 acc = make_float4(0.f, 0.f, 0.f, 0.f);
        #pragma unroll 4
        for (int n = n0 + warp; n < n1; n += NWARP) {
            float4 v = __ldcs(&p[(size_t)n * 32 + lane]);
            acc.x += v.x; acc.y += v.y; acc.z += v.z; acc.w += v.w;
        }
        red[warp * 32 + lane] = acc;
        __syncthreads();
        if (warp == 0) {
            float4 tot = red[lane];
            #pragma unroll
            for (int g = 1; g < NWARP; ++g) {
                float4 v = red[g * 32 + lane];
                tot.x += v.x; tot.y += v.y; tot.z += v.z; tot.w += v.w;
            }
            float* dst = g_s + va * NC + lane * 4;
            atomicAdd(dst + 0, tot.x);
            atomicAdd(dst + 1, tot.y);
            atomicAdd(dst + 2, tot.z);
            atomicAdd(dst + 3, tot.w);
        }
        __syncthreads();
    }

    if (tid == 0) { __threadfence(); atomicAdd(&g_bar1, 1u); }

    // ---------------- Prep (block 0): u = (s/N)W, t = (s/N).b ----------------
    if (blk == 0) {
        if (tid == 0) {
            while (atomicAdd(&g_bar1, 0u) < (unsigned)NBLK) __nanosleep(64);
        }
        __syncthreads();
        __threadfence();

        float* sh_s = reinterpret_cast<float*>(red);
        for (int i = tid; i < NVA * NC; i += NTHR) {
            float v = __ldcg(&g_s[i]);          // coherent read of atomics (L2)
            sh_s[i] = v * (1.0f / (float)NN);
            g_s[i]  = 0.f;                       // reset for next launch
        }
        __syncthreads();

        for (int idx = tid; idx < NVA * NC; idx += NTHR) {
            const int va = idx >> 7, c = idx & 127, v = va >> 2;
            const float* __restrict__ Wv = W + (size_t)v * NC * NC;
            const float* __restrict__ sv = sh_s + va * NC;
            float a0 = 0.f, a1 = 0.f, a2 = 0.f, a3 = 0.f;
            #pragma unroll 8
            for (int d = 0; d < NC; d += 4) {
                a0 += sv[d + 0] * __ldg(&Wv[(d + 0) * NC + c]);
                a1 += sv[d + 1] * __ldg(&Wv[(d + 1) * NC + c]);
                a2 += sv[d + 2] * __ldg(&Wv[(d + 2) * NC + c]);
                a3 += sv[d + 3] * __ldg(&Wv[(d + 3) * NC + c]);
            }
            g_u[idx] = (a0 + a1) + (a2 + a3);
        }
        if (warp < NVA) {
            const float* sv = sh_s + warp * NC;
            const float* bv = b + (warp >> 2) * NC;
            float acc = 0.f;
            #pragma unroll
            for (int d = lane; d < NC; d += 32) acc += sv[d] * bv[d];
            #pragma unroll
            for (int o = 16; o; o >>= 1) acc += __shfl_xor_sync(0xFFFFFFFFu, acc, o);
            if (lane == 0) g_t[warp] = acc;
        }
        __syncthreads();
        if (tid == 0) { __threadfence(); atomicExch(&g_flag, 1u); }
    }

    // ---------------- Wait for u/t, stage into shared ----------------
    if (tid == 0) {
        while (atomicAdd(&g_flag, 0u) == 0u) __nanosleep(64);
    }
    __syncthreads();
    __threadfence();

    {
        const float4* gu4 = reinterpret_cast<const float4*>(g_u);
        for (int i = tid; i < NVA * 32; i += NTHR) sh_u[i] = __ldcg(&gu4[i]);
        for (int i = tid; i < NVA;      i += NTHR) sh_t[i] = __ldcg(&g_t[i]);
    }
    __syncthreads();

    // ---------------- Phase 2: scores -> softmax over views -> combine ------
    const int gw    = blk * NWARP + warp;                       // 0..4735
    const int chunk = (TOTAL + NBLK * NWARP - 1) / (NBLK * NWARP);  // 43
    const int s0    = gw * chunk;
    const int s1    = min(s0 + chunk, TOTAL);
    float4* __restrict__ o4 = reinterpret_cast<float4*>(out);

    for (int idx = s0; idx < s1; ++idx) {
        const int a = idx / NN;                                 // 0..3
        const size_t base = (size_t)idx * 32 + lane;

        const float4 x0 = __ldcs(&x4[base]);
        const float4 x1 = __ldcs(&x4[base + (size_t)TOTAL * 32]);
        const float4 x2 = __ldcs(&x4[base + (size_t)2 * TOTAL * 32]);

        const float4 u0 = sh_u[(0 * NA + a) * 32 + lane];
        const float4 u1 = sh_u[(1 * NA + a) * 32 + lane];
        const float4 u2 = sh_u[(2 * NA + a) * 32 + lane];

        float p0 = x0.x * u0.x + x0.y * u0.y + x0.z * u0.z + x0.w * u0.w;
        float p1 = x1.x * u1.x + x1.y * u1.y + x1.z * u1.z + x1.w * u1.w;
        float p2 = x2.x * u2.x + x2.y * u2.y + x2.z * u2.z + x2.w * u2.w;

        #pragma unroll
        for (int o = 16; o; o >>= 1) {
            p0 += __shfl_xor_sync(0xFFFFFFFFu, p0, o);
            p1 += __shfl_xor_sync(0xFFFFFFFFu, p1, o);
            p2 += __shfl_xor_sync(0xFFFFFFFFu, p2, o);
        }
        p0 += sh_t[0 * NA + a];
        p1 += sh_t[1 * NA + a];
        p2 += sh_t[2 * NA + a];

        // tanh(p) = 2/(1+e^{-2p}) - 1 (MUFU path), then exp for softmax
        const float th0 = __fdividef(2.f, 1.f + __expf(-2.f * p0)) - 1.f;
        const float th1 = __fdividef(2.f, 1.f + __expf(-2.f * p1)) - 1.f;
        const float th2 = __fdividef(2.f, 1.f + __expf(-2.f * p2)) - 1.f;
        const float e0 = __expf(th0);
        const float e1 = __expf(th1);
        const float e2 = __expf(th2);
        const float inv = __fdividef(1.f, e0 + e1 + e2);
        const float w0 = e0 * inv, w1 = e1 * inv, w2 = e2 * inv;

        float4 o;
        o.x = w0 * x0.x + w1 * x1.x + w2 * x2.x;
        o.y = w0 * x0.y + w1 * x1.y + w2 * x2.y;
        o.z = w0 * x0.z + w1 * x1.z + w2 * x2.z;
        o.w = w0 * x0.w + w1 * x1.w + w2 * x2.w;
        __stcs(&o4[base], o);
    }

    // ---------------- Reset barrier words for the next replay ----------------
    __syncthreads();
    if (tid == 0) {
        if (atomicAdd(&g_bar2, 1u) == (unsigned)(NBLK - 1)) {
            atomicExch(&g_bar1, 0u);
            atomicExch(&g_flag, 0u);
            __threadfence();
            atomicExch(&g_bar2, 0u);
        }
    }
}

extern "C" void kernel_launch(void* const* d_in, const int* in_sizes, int n_in,
                              void* d_out, int out_size) {
    const float* x  = (const float*)d_in[0];   // [V,A,N,C]
    const float* Wm = (const float*)d_in[1];   // [V,C,C]
    const float* b  = (const float*)d_in[2];   // [V,C]
    float* out = (float*)d_out;                // [A,N,C]
    (void)in_sizes; (void)n_in; (void)out_size;

    fused_kernel<<<NBLK, NTHR>>>(x, Wm, b, out);
}